// round 1
// baseline (speedup 1.0000x reference)
#include <cuda_runtime.h>

typedef unsigned long long ull;

#define HW 128
#define KSZ 255
#define CCH 256

__device__ __forceinline__ void fma2(ull &d, ull a, ull b) {
    asm("fma.rn.f32x2 %0, %1, %2, %0;" : "+l"(d) : "l"(a), "l"(b));
}
__device__ __forceinline__ ull dup2(float v) {
    ull r; asm("mov.b64 %0, {%1, %1};" : "=l"(r) : "f"(v)); return r;
}
__device__ __forceinline__ float lo32(ull v) { return __uint_as_float((unsigned)v); }
__device__ __forceinline__ float hi32(ull v) { return __uint_as_float((unsigned)(v >> 32)); }

// XOR-chunk swizzle: phys = row*128 + (col ^ swz(row)), swz touches col bits [2:4]
__device__ __forceinline__ int swz(int row) { return ((row >> 2) & 7) << 2; }

union F4U { float4 f; ull u[2]; };

// One Toeplitz-conv stage: acc[a][p] += buf-row-mm.
// Thread tile: rows r0..r0+7 (output dim), cols {c1..c1+3, c2..c2+3} (preserved dim).
// acc pairs are along the column dim: p=0:(c1,c1+1) p=1:(c1+2,c1+3) p=2:(c2,c2+1) p=3:(c2+2,c2+3)
__device__ __forceinline__ void stage(const float* __restrict__ sbuf,
                                      const float* __restrict__ ws,
                                      float bias, int r0, int c1, int c2,
                                      ull acc[8][4]) {
    ull b2 = dup2(bias);
#pragma unroll
    for (int a = 0; a < 8; a++)
#pragma unroll
        for (int p = 0; p < 4; p++) acc[a][p] = b2;

#pragma unroll 1
    for (int ic = 0; ic < HW; ic += 8) {
        // sliding weight window: wd[k] = ws[120 + ic - r0 + k], k in [0,14]
        ull wd[15];
        int wbase = 120 + ic - r0;
#pragma unroll
        for (int k = 0; k < 15; k++) wd[k] = dup2(ws[wbase + k]);

#pragma unroll
        for (int di = 0; di < 8; di++) {
            int i = ic + di;
            const float* rowp = &sbuf[i * HW];
            int s = swz(i);
            F4U ua, ub;
            ua.f = *(const float4*)&rowp[c1 ^ s];
            ub.f = *(const float4*)&rowp[c2 ^ s];
            ull x0 = ua.u[0], x1 = ua.u[1], x2 = ub.u[0], x3 = ub.u[1];
#pragma unroll
            for (int a = 0; a < 8; a++) {
                ull w2 = wd[di + 7 - a];
                fma2(acc[a][0], x0, w2);
                fma2(acc[a][1], x1, w2);
                fma2(acc[a][2], x2, w2);
                fma2(acc[a][3], x3, w2);
            }
        }
    }
}

// Store acc transposed into sbuf: sbuf[col][row] layout (row becomes the minor dim).
// For each logical col (8 of them) store two float4s over a=0..3 / a=4..7.
__device__ __forceinline__ void store_T(float* __restrict__ sbuf,
                                        ull acc[8][4], int r0, int c1, int c2) {
#pragma unroll
    for (int half = 0; half < 2; half++) {
        int cb = half ? c2 : c1;
#pragma unroll
        for (int k = 0; k < 4; k++) {
            int col = cb + k;
            int p = half * 2 + (k >> 1);
            float4 v0, v1;
            if (k & 1) {
                v0 = make_float4(hi32(acc[0][p]), hi32(acc[1][p]), hi32(acc[2][p]), hi32(acc[3][p]));
                v1 = make_float4(hi32(acc[4][p]), hi32(acc[5][p]), hi32(acc[6][p]), hi32(acc[7][p]));
            } else {
                v0 = make_float4(lo32(acc[0][p]), lo32(acc[1][p]), lo32(acc[2][p]), lo32(acc[3][p]));
                v1 = make_float4(lo32(acc[4][p]), lo32(acc[5][p]), lo32(acc[6][p]), lo32(acc[7][p]));
            }
            int s = swz(col);
            *(float4*)&sbuf[col * HW + (r0 ^ s)] = v0;
            *(float4*)&sbuf[col * HW + ((r0 + 4) ^ s)] = v1;
        }
    }
}

extern "C" __global__ void __launch_bounds__(256)
conv_sep_kernel(const float* __restrict__ x,
                const float* __restrict__ wh, const float* __restrict__ bh,
                const float* __restrict__ ww, const float* __restrict__ bw,
                float* __restrict__ out) {
    extern __shared__ __align__(16) float smem[];
    float* xs  = smem;            // 128*128 floats, reused as Y^T then Z
    float* whs = smem + HW * HW;  // 256
    float* wws = whs + 256;       // 256

    int t = threadIdx.x;
    int img = blockIdx.x;
    int c = img & (CCH - 1);
    size_t base = (size_t)img * (HW * HW);

    if (t < KSZ) {
        whs[t] = wh[c * KSZ + t];
        wws[t] = ww[c * KSZ + t];
    }
    float biash = bh[c], biasw = bw[c];

    // fill xs with swizzled image
    const float4* gx = (const float4*)(x + base);
#pragma unroll
    for (int r = 0; r < 16; r++) {
        int g = t + 256 * r;
        int row = g >> 5, ch = g & 31;
        float4 v = gx[g];
        *(float4*)&xs[row * HW + 4 * (ch ^ ((row >> 2) & 7))] = v;
    }
    __syncthreads();

    int tc = t & 15, tr = t >> 4;
    int r0 = tr * 8;
    int c1 = 4 * tc, c2 = 64 + 4 * tc;

    ull acc[8][4];

    // stage 1: H-conv. rows = h, cols = w. result Y[h][w] in regs.
    stage(xs, whs, biash, r0, c1, c2, acc);
    __syncthreads();
    // store Y transposed: buffer becomes Yt[w][h]
    store_T(xs, acc, r0, c1, c2);
    __syncthreads();

    // stage 2: W-conv on Yt. rows = w', cols = h. result Zt[w'][h] in regs.
    stage(xs, wws, biasw, r0, c1, c2, acc);
    __syncthreads();
    // store Z transposed back to natural layout: buffer becomes Z[h][w']
    store_T(xs, acc, r0, c1, c2);
    __syncthreads();

    // coalesced write-out
    float4* go = (float4*)(out + base);
#pragma unroll
    for (int r = 0; r < 16; r++) {
        int g = t + 256 * r;
        int row = g >> 5, ch = g & 31;
        float4 v = *(const float4*)&xs[row * HW + 4 * (ch ^ ((row >> 2) & 7))];
        go[g] = v;
    }
}

extern "C" void kernel_launch(void* const* d_in, const int* in_sizes, int n_in,
                              void* d_out, int out_size) {
    const float* x  = (const float*)d_in[0];
    const float* wh = (const float*)d_in[1];
    const float* bh = (const float*)d_in[2];
    const float* ww = (const float*)d_in[3];
    const float* bw = (const float*)d_in[4];
    float* out = (float*)d_out;

    int nimg = in_sizes[0] >> 14;  // elements / (128*128)
    size_t smem_bytes = (HW * HW + 512) * sizeof(float);  // 67584
    cudaFuncSetAttribute(conv_sep_kernel,
                         cudaFuncAttributeMaxDynamicSharedMemorySize,
                         (int)smem_bytes);
    conv_sep_kernel<<<nimg, 256, smem_bytes>>>(x, wh, bh, ww, bw, out);
}

// round 2
// speedup vs baseline: 1.0866x; 1.0866x over previous
#include <cuda_runtime.h>

typedef unsigned long long ull;

#define HW 128
#define KSZ 255
#define CCH 256

__device__ __forceinline__ void fma2(ull &d, ull a, ull b) {
    asm("fma.rn.f32x2 %0, %1, %2, %0;" : "+l"(d) : "l"(a), "l"(b));
}
__device__ __forceinline__ ull dup2(float v) {
    ull r; asm("mov.b64 %0, {%1, %1};" : "=l"(r) : "f"(v)); return r;
}
__device__ __forceinline__ float lo32(ull v) { return __uint_as_float((unsigned)v); }
__device__ __forceinline__ float hi32(ull v) { return __uint_as_float((unsigned)(v >> 32)); }

// XOR-chunk swizzle: phys = row*128 + (col ^ swz(row)), swz touches col bits [2:4]
__device__ __forceinline__ int swz(int row) { return ((row >> 2) & 7) << 2; }

union F4U { float4 f; ull u[2]; };

// One Toeplitz-conv stage: y[r] = bias + sum_i x[i] * w[127 + i - r]
// Thread tile: rows r0..r0+7 (conv dim), cols {c1..c1+3, c2..c2+3} (preserved dim).
__device__ __forceinline__ void stage(const float* __restrict__ sbuf,
                                      const float* __restrict__ ws,
                                      float bias, int r0, int c1, int c2,
                                      ull acc[8][4]) {
    ull b2 = dup2(bias);
#pragma unroll
    for (int a = 0; a < 8; a++)
#pragma unroll
        for (int p = 0; p < 4; p++) acc[a][p] = b2;

#pragma unroll 1
    for (int ic = 0; ic < HW; ic += 8) {
        // sliding weight window: wd[k] = ws[120 + ic - r0 + k], k in [0,14]
        ull wd[15];
        int wbase = 120 + ic - r0;
#pragma unroll
        for (int k = 0; k < 15; k++) wd[k] = dup2(ws[wbase + k]);

#pragma unroll
        for (int di = 0; di < 8; di++) {
            int i = ic + di;
            const float* rowp = &sbuf[i * HW];
            int s = swz(i);
            F4U ua, ub;
            ua.f = *(const float4*)&rowp[c1 ^ s];
            ub.f = *(const float4*)&rowp[c2 ^ s];
            ull x0 = ua.u[0], x1 = ua.u[1], x2 = ub.u[0], x3 = ub.u[1];
#pragma unroll
            for (int a = 0; a < 8; a++) {
                ull w2 = wd[di + 7 - a];
                fma2(acc[a][0], x0, w2);
                fma2(acc[a][1], x1, w2);
                fma2(acc[a][2], x2, w2);
                fma2(acc[a][3], x3, w2);
            }
        }
    }
}

// Store acc transposed into sbuf: sbuf[col][row] layout.
__device__ __forceinline__ void store_T(float* __restrict__ sbuf,
                                        ull acc[8][4], int r0, int c1, int c2) {
#pragma unroll
    for (int half = 0; half < 2; half++) {
        int cb = half ? c2 : c1;
#pragma unroll
        for (int k = 0; k < 4; k++) {
            int col = cb + k;
            int p = half * 2 + (k >> 1);
            float4 v0, v1;
            if (k & 1) {
                v0 = make_float4(hi32(acc[0][p]), hi32(acc[1][p]), hi32(acc[2][p]), hi32(acc[3][p]));
                v1 = make_float4(hi32(acc[4][p]), hi32(acc[5][p]), hi32(acc[6][p]), hi32(acc[7][p]));
            } else {
                v0 = make_float4(lo32(acc[0][p]), lo32(acc[1][p]), lo32(acc[2][p]), lo32(acc[3][p]));
                v1 = make_float4(lo32(acc[4][p]), lo32(acc[5][p]), lo32(acc[6][p]), lo32(acc[7][p]));
            }
            int s = swz(col);
            *(float4*)&sbuf[col * HW + (r0 ^ s)] = v0;
            *(float4*)&sbuf[col * HW + ((r0 + 4) ^ s)] = v1;
        }
    }
}

extern "C" __global__ void __launch_bounds__(256, 2)
conv_sep_kernel(const float* __restrict__ x,
                const float* __restrict__ wh, const float* __restrict__ bh,
                const float* __restrict__ ww, const float* __restrict__ bw,
                float* __restrict__ out) {
    extern __shared__ __align__(16) float smem[];
    float* xs  = smem;            // 128*128 floats, reused as Y^T then Z
    float* whs = smem + HW * HW;  // 256
    float* wws = whs + 256;       // 256

    int t = threadIdx.x;
    int img = blockIdx.x;
    int c = img & (CCH - 1);
    size_t base = (size_t)img * (HW * HW);

    if (t < KSZ) {
        whs[t] = wh[c * KSZ + t];
        wws[t] = ww[c * KSZ + t];
    }
    float biash = bh[c], biasw = bw[c];

    // fill xs with swizzled image
    const float4* gx = (const float4*)(x + base);
#pragma unroll
    for (int r = 0; r < 16; r++) {
        int g = t + 256 * r;
        int row = g >> 5, ch = g & 31;
        float4 v = gx[g];
        *(float4*)&xs[row * HW + 4 * (ch ^ ((row >> 2) & 7))] = v;
    }
    __syncthreads();

    int tc = t & 15, tr = t >> 4;
    int r0 = tr * 8;
    int c1 = 4 * tc, c2 = 64 + 4 * tc;

    ull acc[8][4];

    // stage 1: H-conv. rows = h, cols = w. result Y[h][w] in regs.
    stage(xs, whs, biash, r0, c1, c2, acc);
    __syncthreads();
    // store Y transposed: buffer becomes Yt[w][h]
    store_T(xs, acc, r0, c1, c2);
    __syncthreads();

    // stage 2: W-conv on Yt. rows = w', cols = h. result Zt[w'][h] in regs.
    stage(xs, wws, biasw, r0, c1, c2, acc);
    __syncthreads();
    // store Z transposed back to natural layout: buffer becomes Z[h][w']
    store_T(xs, acc, r0, c1, c2);
    __syncthreads();

    // coalesced write-out
    float4* go = (float4*)(out + base);
#pragma unroll
    for (int r = 0; r < 16; r++) {
        int g = t + 256 * r;
        int row = g >> 5, ch = g & 31;
        float4 v = *(const float4*)&xs[row * HW + 4 * (ch ^ ((row >> 2) & 7))];
        go[g] = v;
    }
}

extern "C" void kernel_launch(void* const* d_in, const int* in_sizes, int n_in,
                              void* d_out, int out_size) {
    const float* x  = (const float*)d_in[0];
    const float* wh = (const float*)d_in[1];
    const float* bh = (const float*)d_in[2];
    const float* ww = (const float*)d_in[3];
    const float* bw = (const float*)d_in[4];
    float* out = (float*)d_out;

    int nimg = in_sizes[0] >> 14;  // elements / (128*128)
    size_t smem_bytes = (HW * HW + 512) * sizeof(float);  // 67584
    cudaFuncSetAttribute(conv_sep_kernel,
                         cudaFuncAttributeMaxDynamicSharedMemorySize,
                         (int)smem_bytes);
    conv_sep_kernel<<<nimg, 256, smem_bytes>>>(x, wh, bh, ww, bw, out);
}

// round 4
// speedup vs baseline: 1.4383x; 1.3237x over previous
#include <cuda_runtime.h>
#include <cuda_bf16.h>
#include <cstdint>

#define HW 128
#define KSZ 255

// smem byte offsets
#define OFF_WHH 0
#define OFF_WHL 512
#define OFF_WWH 1024
#define OFF_WWL 1536
#define OFF_AH  4096
#define OFF_AL  (OFF_AH + 32768)
#define OFF_BH  (OFF_AH + 65536)
#define OFF_BL  (OFF_AH + 98304)
#define SMEM_TOTAL (OFF_AH + 131072)

// K-major bf16 plane: 128 rows x 256B. 16B chunks XOR-swizzled by row&7.
__device__ __forceinline__ uint32_t off_rk(int r, int k) {
    return (uint32_t)(r * 256 + ((((k >> 3) ^ (r & 7)) << 4) | ((k & 7) << 1)));
}

__device__ __forceinline__ uint32_t s2u(const void* p) {
    uint32_t a;
    asm("{ .reg .u64 t; cvta.to.shared.u64 t, %1; cvt.u32.u64 %0, t; }" : "=r"(a) : "l"(p));
    return a;
}

__device__ __forceinline__ void ldsm4(uint32_t* r, uint32_t a) {
    asm volatile("ldmatrix.sync.aligned.m8n8.x4.shared.b16 {%0,%1,%2,%3},[%4];"
                 : "=r"(r[0]), "=r"(r[1]), "=r"(r[2]), "=r"(r[3]) : "r"(a));
}

__device__ __forceinline__ void mma_bf16(float* d, uint32_t a0, uint32_t a1, uint32_t a2,
                                         uint32_t a3, uint32_t b0, uint32_t b1) {
    asm volatile(
        "mma.sync.aligned.m16n8k16.row.col.f32.bf16.bf16.f32 "
        "{%0,%1,%2,%3},{%4,%5,%6,%7},{%8,%9},{%0,%1,%2,%3};"
        : "+f"(d[0]), "+f"(d[1]), "+f"(d[2]), "+f"(d[3])
        : "r"(a0), "r"(a1), "r"(a2), "r"(a3), "r"(b0), "r"(b1));
}

__device__ __forceinline__ void bsplit(float v, unsigned short& h, unsigned short& l) {
    __nv_bfloat16 bh_ = __float2bfloat16(v);
    float r = v - __bfloat162float(bh_);
    __nv_bfloat16 bl_ = __float2bfloat16(r);
    h = __bfloat16_as_ushort(bh_);
    l = __bfloat16_as_ushort(bl_);
}
__device__ __forceinline__ uint32_t pck(unsigned short a, unsigned short b) {
    return (uint32_t)a | ((uint32_t)b << 16);
}

// Build Toeplitz operand T[r][k] = w[127 + k - r] into hi/lo planes.
__device__ __forceinline__ void build_toep(char* smem, uint32_t dH, uint32_t dL,
                                           const unsigned short* sh,
                                           const unsigned short* sl, int t) {
#pragma unroll 4
    for (int it = 0; it < 32; it++) {
        int id = t + 256 * it;
        int r = id >> 6, k0 = (id & 63) << 1;
        int i0 = 127 + k0 - r;
        uint32_t a = off_rk(r, k0);
        *(uint32_t*)(smem + dH + a) = pck(sh[i0], sh[i0 + 1]);
        *(uint32_t*)(smem + dL + a) = pck(sl[i0], sl[i0 + 1]);
    }
}

// One 128x128x(3x128) stage. d[tm][tn][4] accumulators (already bias-initialized).
__device__ __forceinline__ void gemm_stage(uint32_t aH, uint32_t aL, uint32_t bH, uint32_t bL,
                                           float d[4][4][4], int lane, int mwb, int nwb) {
    int liA = lane & 15, khA = lane >> 4;
    int nB = lane & 7, khB = (lane & 15) >> 3, tB = lane >> 4;
    uint32_t aRow = (uint32_t)(mwb + liA) * 256;
    uint32_t bRow = (uint32_t)(nwb + 8 * tB + nB) * 256;

#pragma unroll
    for (int pass = 0; pass < 3; pass++) {
        uint32_t aP = (pass < 2) ? aH : aL;
        uint32_t bP = (pass == 1) ? bL : bH;
#pragma unroll
        for (int kk = 0; kk < 8; kk++) {
            uint32_t ax = (uint32_t)(((2 * kk + khA) ^ (liA & 7)) << 4);
            uint32_t bx = (uint32_t)(((2 * kk + khB) ^ nB) << 4);
            uint32_t a_base = aP + aRow + ax;
            uint32_t b_base = bP + bRow + bx;
            uint32_t af[4][4];
#pragma unroll
            for (int tm = 0; tm < 4; tm++) ldsm4(af[tm], a_base + tm * 4096);
            uint32_t bf[2][4];
#pragma unroll
            for (int tp = 0; tp < 2; tp++) ldsm4(bf[tp], b_base + tp * 4096);
#pragma unroll
            for (int tm = 0; tm < 4; tm++)
#pragma unroll
                for (int tn = 0; tn < 4; tn++)
                    mma_bf16(d[tm][tn], af[tm][0], af[tm][1], af[tm][2], af[tm][3],
                             bf[tn >> 1][(tn & 1) * 2], bf[tn >> 1][(tn & 1) * 2 + 1]);
        }
    }
}

extern "C" __global__ void __launch_bounds__(256)
conv_mma_kernel(const float* __restrict__ x,
                const float* __restrict__ wh, const float* __restrict__ bh,
                const float* __restrict__ ww, const float* __restrict__ bw,
                float* __restrict__ out) {
    extern __shared__ __align__(1024) char smem[];
    uint32_t sb = s2u(smem);
    int t = threadIdx.x, lane = t & 31, wid = t >> 5;
    int img = blockIdx.x, c = img & 255;
    size_t base = (size_t)img << 14;

    unsigned short* whh = (unsigned short*)(smem + OFF_WHH);
    unsigned short* whl = (unsigned short*)(smem + OFF_WHL);
    unsigned short* wwh = (unsigned short*)(smem + OFF_WWH);
    unsigned short* wwl = (unsigned short*)(smem + OFF_WWL);
    if (t < KSZ) {
        unsigned short h_, l_;
        bsplit(wh[c * KSZ + t], h_, l_); whh[t] = h_; whl[t] = l_;
        bsplit(ww[c * KSZ + t], h_, l_); wwh[t] = h_; wwl[t] = l_;
    }
    float bhc = bh[c], bwc = bw[c];
    __syncthreads();

    // A = Toep(wh)
    build_toep(smem, OFF_AH, OFF_AL, whh, whl, t);

    // B = X^T : B[w][i] = X[i][w], staggered i to avoid STS bank conflicts
    {
        int w = t & 127, half = t >> 7;
        int g = (t >> 3) & 3;  // lane>>3 stagger group
        const float* xp = x + base + w;
#pragma unroll 4
        for (int it = 0; it < 32; it++) {
            int i0 = half * 64 + ((2 * it + g * 16) & 63);
            float f0 = xp[(size_t)i0 * HW];
            float f1 = xp[(size_t)i0 * HW + HW];
            unsigned short h0, l0, h1, l1;
            bsplit(f0, h0, l0); bsplit(f1, h1, l1);
            uint32_t a = off_rk(w, i0);
            *(uint32_t*)(smem + OFF_BH + a) = pck(h0, h1);
            *(uint32_t*)(smem + OFF_BL + a) = pck(l0, l1);
        }
    }
    __syncthreads();

    int wm = wid >> 2, wn = wid & 3;
    int mwb = wm * 64, nwb = wn * 32;

    float d[4][4][4];
#pragma unroll
    for (int tm = 0; tm < 4; tm++)
#pragma unroll
        for (int tn = 0; tn < 4; tn++)
#pragma unroll
            for (int q = 0; q < 4; q++) d[tm][tn][q] = bhc;

    // Stage 1: Y = Toep(wh) @ X^T^T  -> Y[h][w]
    gemm_stage(sb + OFF_AH, sb + OFF_AL, sb + OFF_BH, sb + OFF_BL, d, lane, mwb, nwb);
    __syncthreads();

    // Mid-epilogue: Y -> bf16 hi/lo into A planes (k-major [h][w])
    {
        int ro = lane >> 2, co = (lane & 3) * 2;
#pragma unroll
        for (int tm = 0; tm < 4; tm++)
#pragma unroll
            for (int tn = 0; tn < 4; tn++) {
                int r0 = mwb + tm * 16 + ro;
                int c0 = nwb + tn * 8 + co;
                unsigned short h0, l0, h1, l1;
                bsplit(d[tm][tn][0], h0, l0);
                bsplit(d[tm][tn][1], h1, l1);
                uint32_t a = off_rk(r0, c0);
                *(uint32_t*)(smem + OFF_AH + a) = pck(h0, h1);
                *(uint32_t*)(smem + OFF_AL + a) = pck(l0, l1);
                bsplit(d[tm][tn][2], h0, l0);
                bsplit(d[tm][tn][3], h1, l1);
                a = off_rk(r0 + 8, c0);
                *(uint32_t*)(smem + OFF_AH + a) = pck(h0, h1);
                *(uint32_t*)(smem + OFF_AL + a) = pck(l0, l1);
            }
    }
    // B planes = Toep(ww)
    build_toep(smem, OFF_BH, OFF_BL, wwh, wwl, t);
    __syncthreads();

#pragma unroll
    for (int tm = 0; tm < 4; tm++)
#pragma unroll
        for (int tn = 0; tn < 4; tn++)
#pragma unroll
            for (int q = 0; q < 4; q++) d[tm][tn][q] = bwc;

    // Stage 2: Z[h][w'] = Y @ Toep(ww)^T
    gemm_stage(sb + OFF_AH, sb + OFF_AL, sb + OFF_BH, sb + OFF_BL, d, lane, mwb, nwb);

    // Final epilogue: direct global float2 stores
    {
        int ro = lane >> 2, co = (lane & 3) * 2;
#pragma unroll
        for (int tm = 0; tm < 4; tm++)
#pragma unroll
            for (int tn = 0; tn < 4; tn++) {
                int r0 = mwb + tm * 16 + ro;
                int c0 = nwb + tn * 8 + co;
                float2 v0 = make_float2(d[tm][tn][0], d[tm][tn][1]);
                float2 v1 = make_float2(d[tm][tn][2], d[tm][tn][3]);
                *(float2*)(out + base + (size_t)r0 * HW + c0) = v0;
                *(float2*)(out + base + (size_t)(r0 + 8) * HW + c0) = v1;
            }
    }
}

extern "C" void kernel_launch(void* const* d_in, const int* in_sizes, int n_in,
                              void* d_out, int out_size) {
    const float* x  = (const float*)d_in[0];
    const float* wh = (const float*)d_in[1];
    const float* bh = (const float*)d_in[2];
    const float* ww = (const float*)d_in[3];
    const float* bw = (const float*)d_in[4];
    float* out = (float*)d_out;

    int nimg = in_sizes[0] >> 14;
    cudaFuncSetAttribute(conv_mma_kernel,
                         cudaFuncAttributeMaxDynamicSharedMemorySize, SMEM_TOTAL);
    conv_mma_kernel<<<nimg, 256, SMEM_TOTAL>>>(x, wh, bh, ww, bw, out);
}

// round 5
// speedup vs baseline: 1.7171x; 1.1938x over previous
#include <cuda_runtime.h>
#include <cuda_bf16.h>
#include <cstdint>

#define HW 128
#define KSZ 255
#define NTHR 512

// smem byte offsets
#define OFF_WHH 0
#define OFF_WHL 512
#define OFF_WWH 1024
#define OFF_WWL 1536
#define OFF_AH  4096
#define OFF_AL  (OFF_AH + 32768)
#define OFF_BH  (OFF_AH + 65536)
#define OFF_BL  (OFF_AH + 98304)
#define SMEM_TOTAL (OFF_AH + 131072)

// K-major bf16 plane: 128 rows x 256B. 16B chunks XOR-swizzled by row&7.
__device__ __forceinline__ uint32_t off_rk(int r, int k) {
    return (uint32_t)(r * 256 + ((((k >> 3) ^ (r & 7)) << 4) | ((k & 7) << 1)));
}

__device__ __forceinline__ uint32_t s2u(const void* p) {
    uint32_t a;
    asm("{ .reg .u64 t; cvta.to.shared.u64 t, %1; cvt.u32.u64 %0, t; }" : "=r"(a) : "l"(p));
    return a;
}

__device__ __forceinline__ void ldsm4(uint32_t* r, uint32_t a) {
    asm volatile("ldmatrix.sync.aligned.m8n8.x4.shared.b16 {%0,%1,%2,%3},[%4];"
                 : "=r"(r[0]), "=r"(r[1]), "=r"(r[2]), "=r"(r[3]) : "r"(a));
}

__device__ __forceinline__ void mma_bf16(float* d, const uint32_t* a, uint32_t b0, uint32_t b1) {
    asm volatile(
        "mma.sync.aligned.m16n8k16.row.col.f32.bf16.bf16.f32 "
        "{%0,%1,%2,%3},{%4,%5,%6,%7},{%8,%9},{%0,%1,%2,%3};"
        : "+f"(d[0]), "+f"(d[1]), "+f"(d[2]), "+f"(d[3])
        : "r"(a[0]), "r"(a[1]), "r"(a[2]), "r"(a[3]), "r"(b0), "r"(b1));
}

__device__ __forceinline__ void bsplit(float v, unsigned short& h, unsigned short& l) {
    __nv_bfloat16 bh_ = __float2bfloat16(v);
    float r = v - __bfloat162float(bh_);
    __nv_bfloat16 bl_ = __float2bfloat16(r);
    h = __bfloat16_as_ushort(bh_);
    l = __bfloat16_as_ushort(bl_);
}
__device__ __forceinline__ uint32_t pck(unsigned short a, unsigned short b) {
    return (uint32_t)a | ((uint32_t)b << 16);
}

// Build Toeplitz operand T[r][k] = w[127 + k - r] into hi/lo planes.
__device__ __forceinline__ void build_toep(char* smem, uint32_t dH, uint32_t dL,
                                           const unsigned short* sh,
                                           const unsigned short* sl, int t) {
#pragma unroll 4
    for (int it = 0; it < 16; it++) {
        int id = t + NTHR * it;
        int r = id >> 6, k0 = (id & 63) << 1;
        int i0 = 127 + k0 - r;
        uint32_t a = off_rk(r, k0);
        *(uint32_t*)(smem + dH + a) = pck(sh[i0], sh[i0 + 1]);
        *(uint32_t*)(smem + dL + a) = pck(sl[i0], sl[i0 + 1]);
    }
}

// Fused 3-pass stage: per k-step load AH/AL/BH/BL frags once, issue 24 MMAs.
// Warp tile 32x32: tm in {0,1} (m16 blocks), tn in {0..3} (n8 blocks).
__device__ __forceinline__ void gemm_stage(uint32_t aH, uint32_t aL, uint32_t bH, uint32_t bL,
                                           float d[2][4][4], int lane, int mwb, int nwb) {
    int liA = lane & 15, khA = lane >> 4;
    int nB = lane & 7, khB = (lane & 15) >> 3, tB = lane >> 4;
    uint32_t aOff = (uint32_t)(mwb + liA) * 256;
    uint32_t bOff = (uint32_t)(nwb + 8 * tB + nB) * 256;

#pragma unroll
    for (int kk = 0; kk < 8; kk++) {
        uint32_t ax = (uint32_t)(((2 * kk + khA) ^ (liA & 7)) << 4);
        uint32_t bx = (uint32_t)(((2 * kk + khB) ^ nB) << 4);
        uint32_t ah[2][4], al[2][4], bh_[2][4], bl_[2][4];
#pragma unroll
        for (int tm = 0; tm < 2; tm++) {
            ldsm4(ah[tm], aH + aOff + ax + tm * 4096);
            ldsm4(al[tm], aL + aOff + ax + tm * 4096);
        }
#pragma unroll
        for (int tp = 0; tp < 2; tp++) {
            ldsm4(bh_[tp], bH + bOff + bx + tp * 4096);
            ldsm4(bl_[tp], bL + bOff + bx + tp * 4096);
        }
#pragma unroll
        for (int tm = 0; tm < 2; tm++)
#pragma unroll
            for (int tn = 0; tn < 4; tn++) {
                uint32_t b0h = bh_[tn >> 1][(tn & 1) * 2], b1h = bh_[tn >> 1][(tn & 1) * 2 + 1];
                uint32_t b0l = bl_[tn >> 1][(tn & 1) * 2], b1l = bl_[tn >> 1][(tn & 1) * 2 + 1];
                mma_bf16(d[tm][tn], ah[tm], b0h, b1h);   // hi*hi
                mma_bf16(d[tm][tn], ah[tm], b0l, b1l);   // hi*lo
                mma_bf16(d[tm][tn], al[tm], b0h, b1h);   // lo*hi
            }
    }
}

extern "C" __global__ void __launch_bounds__(NTHR, 1)
conv_mma_kernel(const float* __restrict__ x,
                const float* __restrict__ wh, const float* __restrict__ bh,
                const float* __restrict__ ww, const float* __restrict__ bw,
                float* __restrict__ out) {
    extern __shared__ __align__(1024) char smem[];
    uint32_t sb = s2u(smem);
    int t = threadIdx.x, lane = t & 31, wid = t >> 5;
    int img = blockIdx.x, c = img & 255;
    size_t base = (size_t)img << 14;

    unsigned short* whh = (unsigned short*)(smem + OFF_WHH);
    unsigned short* whl = (unsigned short*)(smem + OFF_WHL);
    unsigned short* wwh = (unsigned short*)(smem + OFF_WWH);
    unsigned short* wwl = (unsigned short*)(smem + OFF_WWL);
    if (t < KSZ) {
        unsigned short h_, l_;
        bsplit(wh[c * KSZ + t], h_, l_); whh[t] = h_; whl[t] = l_;
        bsplit(ww[c * KSZ + t], h_, l_); wwh[t] = h_; wwl[t] = l_;
    }
    float bhc = bh[c], bwc = bw[c];
    __syncthreads();

    // A = Toep(wh)
    build_toep(smem, OFF_AH, OFF_AL, whh, whl, t);

    // B = X^T : B[w][i] = X[i][w]; i staggered by lane-octet to avoid STS conflicts
    {
        int w = t & 127, quarter = t >> 7;
        int g = (t >> 3) & 3;
        const float* xp = x + base + w;
#pragma unroll 4
        for (int it = 0; it < 16; it++) {
            int i0 = quarter * 32 + ((2 * it + g * 8) & 31);
            float f0 = xp[(size_t)i0 * HW];
            float f1 = xp[(size_t)i0 * HW + HW];
            unsigned short h0, l0, h1, l1;
            bsplit(f0, h0, l0); bsplit(f1, h1, l1);
            uint32_t a = off_rk(w, i0);
            *(uint32_t*)(smem + OFF_BH + a) = pck(h0, h1);
            *(uint32_t*)(smem + OFF_BL + a) = pck(l0, l1);
        }
    }
    __syncthreads();

    int wm = wid >> 2, wn = wid & 3;
    int mwb = wm * 32, nwb = wn * 32;

    float d[2][4][4];
#pragma unroll
    for (int tm = 0; tm < 2; tm++)
#pragma unroll
        for (int tn = 0; tn < 4; tn++)
#pragma unroll
            for (int q = 0; q < 4; q++) d[tm][tn][q] = bhc;

    // Stage 1: Y[h][w] = Toep(wh) @ X
    gemm_stage(sb + OFF_AH, sb + OFF_AL, sb + OFF_BH, sb + OFF_BL, d, lane, mwb, nwb);
    __syncthreads();

    // Mid-epilogue: Y -> bf16 hi/lo into A planes (k-major [h][w])
    {
        int ro = lane >> 2, co = (lane & 3) * 2;
#pragma unroll
        for (int tm = 0; tm < 2; tm++)
#pragma unroll
            for (int tn = 0; tn < 4; tn++) {
                int r0 = mwb + tm * 16 + ro;
                int c0 = nwb + tn * 8 + co;
                unsigned short h0, l0, h1, l1;
                bsplit(d[tm][tn][0], h0, l0);
                bsplit(d[tm][tn][1], h1, l1);
                uint32_t a = off_rk(r0, c0);
                *(uint32_t*)(smem + OFF_AH + a) = pck(h0, h1);
                *(uint32_t*)(smem + OFF_AL + a) = pck(l0, l1);
                bsplit(d[tm][tn][2], h0, l0);
                bsplit(d[tm][tn][3], h1, l1);
                a = off_rk(r0 + 8, c0);
                *(uint32_t*)(smem + OFF_AH + a) = pck(h0, h1);
                *(uint32_t*)(smem + OFF_AL + a) = pck(l0, l1);
            }
    }
    // B planes = Toep(ww)
    build_toep(smem, OFF_BH, OFF_BL, wwh, wwl, t);
    __syncthreads();

#pragma unroll
    for (int tm = 0; tm < 2; tm++)
#pragma unroll
        for (int tn = 0; tn < 4; tn++)
#pragma unroll
            for (int q = 0; q < 4; q++) d[tm][tn][q] = bwc;

    // Stage 2: Z[h][w'] = Y @ Toep(ww)^T
    gemm_stage(sb + OFF_AH, sb + OFF_AL, sb + OFF_BH, sb + OFF_BL, d, lane, mwb, nwb);

    // Final epilogue: direct global float2 stores
    {
        int ro = lane >> 2, co = (lane & 3) * 2;
#pragma unroll
        for (int tm = 0; tm < 2; tm++)
#pragma unroll
            for (int tn = 0; tn < 4; tn++) {
                int r0 = mwb + tm * 16 + ro;
                int c0 = nwb + tn * 8 + co;
                float2 v0 = make_float2(d[tm][tn][0], d[tm][tn][1]);
                float2 v1 = make_float2(d[tm][tn][2], d[tm][tn][3]);
                *(float2*)(out + base + (size_t)r0 * HW + c0) = v0;
                *(float2*)(out + base + (size_t)(r0 + 8) * HW + c0) = v1;
            }
    }
}

extern "C" void kernel_launch(void* const* d_in, const int* in_sizes, int n_in,
                              void* d_out, int out_size) {
    const float* x  = (const float*)d_in[0];
    const float* wh = (const float*)d_in[1];
    const float* bh = (const float*)d_in[2];
    const float* ww = (const float*)d_in[3];
    const float* bw = (const float*)d_in[4];
    float* out = (float*)d_out;

    int nimg = in_sizes[0] >> 14;
    cudaFuncSetAttribute(conv_mma_kernel,
                         cudaFuncAttributeMaxDynamicSharedMemorySize, SMEM_TOTAL);
    conv_mma_kernel<<<nimg, NTHR, SMEM_TOTAL>>>(x, wh, bh, ww, bw, out);
}

// round 6
// speedup vs baseline: 2.8741x; 1.6738x over previous
#include <cuda_runtime.h>
#include <cuda_fp16.h>
#include <cstdint>

#define HW 128
#define KSZ 255
#define NTHR 256

// smem byte offsets
#define OFF_WHH 0
#define OFF_WHL 512
#define OFF_WWH 1024
#define OFF_WWL 1536
#define OFF_TH  4096             // Toeplitz hi plane (32KB)
#define OFF_TL  (4096 + 32768)   // Toeplitz lo plane (32KB)
#define OFF_X   (4096 + 65536)   // X^T / Y single plane (32KB)
#define SMEM_TOTAL (4096 + 98304)  // 102400 -> 2 CTAs/SM

#define WSCALE 256.0f
#define WINV   0.00390625f

// K-major fp16 plane: 128 rows x 256B; 16B chunks XOR-swizzled by row&7.
__device__ __forceinline__ uint32_t off_rk(int r, int k) {
    return (uint32_t)(r * 256 + ((((k >> 3) ^ (r & 7)) << 4) | ((k & 7) << 1)));
}

__device__ __forceinline__ uint32_t s2u(const void* p) {
    uint32_t a;
    asm("{ .reg .u64 t; cvta.to.shared.u64 t, %1; cvt.u32.u64 %0, t; }" : "=r"(a) : "l"(p));
    return a;
}

__device__ __forceinline__ void ldsm4(uint32_t* r, uint32_t a) {
    asm volatile("ldmatrix.sync.aligned.m8n8.x4.shared.b16 {%0,%1,%2,%3},[%4];"
                 : "=r"(r[0]), "=r"(r[1]), "=r"(r[2]), "=r"(r[3]) : "r"(a));
}

__device__ __forceinline__ void mma_f16(float* d, const uint32_t* a, uint32_t b0, uint32_t b1) {
    asm volatile(
        "mma.sync.aligned.m16n8k16.row.col.f32.f16.f16.f32 "
        "{%0,%1,%2,%3},{%4,%5,%6,%7},{%8,%9},{%0,%1,%2,%3};"
        : "+f"(d[0]), "+f"(d[1]), "+f"(d[2]), "+f"(d[3])
        : "r"(a[0]), "r"(a[1]), "r"(a[2]), "r"(a[3]), "r"(b0), "r"(b1));
}

__device__ __forceinline__ uint32_t pack2(float a, float b) {
    __half2 h = __floats2half2_rn(a, b);
    return *(uint32_t*)&h;
}
__device__ __forceinline__ uint32_t pckh(__half a, __half b) {
    __half2 h = __halves2half2(a, b);
    return *(uint32_t*)&h;
}

// Build Toeplitz operand T[r][k] = ws[127 + k - r] into hi/lo planes.
// Warp-conflict-free: lanes spread over 8 k-chunks x 4 intra-chunk pairs.
__device__ __forceinline__ void build_toep(char* smem, const __half* sh, const __half* sl, int t) {
#pragma unroll 4
    for (int it = 0; it < 32; it++) {
        int id = t + NTHR * it;            // 0..8191
        int r = id >> 6, k0 = (id & 63) << 1;
        int i0 = 127 + k0 - r;
        uint32_t a = off_rk(r, k0);
        *(uint32_t*)(smem + OFF_TH + a) = pckh(sh[i0], sh[i0 + 1]);
        *(uint32_t*)(smem + OFF_TL + a) = pckh(sl[i0], sl[i0 + 1]);
    }
}

extern "C" __global__ void __launch_bounds__(NTHR, 2)
conv_mma_kernel(const float* __restrict__ x,
                const float* __restrict__ wh, const float* __restrict__ bh,
                const float* __restrict__ ww, const float* __restrict__ bw,
                float* __restrict__ out) {
    extern __shared__ __align__(1024) char smem[];
    uint32_t sb = s2u(smem);
    int t = threadIdx.x, lane = t & 31, wid = t >> 5;
    int img = blockIdx.x, c = img & 255;
    size_t base = (size_t)img << 14;

    __half* whh = (__half*)(smem + OFF_WHH);
    __half* whl = (__half*)(smem + OFF_WHL);
    __half* wwh = (__half*)(smem + OFF_WWH);
    __half* wwl = (__half*)(smem + OFF_WWL);
    if (t < KSZ) {
        float v = wh[c * KSZ + t] * WSCALE;
        __half h = __float2half_rn(v);
        whh[t] = h; whl[t] = __float2half_rn(v - __half2float(h));
        v = ww[c * KSZ + t] * WSCALE;
        h = __float2half_rn(v);
        wwh[t] = h; wwl[t] = __float2half_rn(v - __half2float(h));
    }
    float bhc = bh[c] * WSCALE, bwc = bw[c] * WSCALE;

    // X^T single fp16 plane: B[w][i] = f16(X[i][w]); one STS.128 per 8-i chunk.
    {
        int w = t & 127, ihalf = t >> 7;
        const float* xp = x + base + w;
#pragma unroll
        for (int blk = 0; blk < 8; blk++) {
            int i0 = ihalf * 64 + blk * 8;
            uint32_t q[4];
#pragma unroll
            for (int j = 0; j < 4; j++) {
                float f0 = xp[(size_t)(i0 + 2 * j) * HW];
                float f1 = xp[(size_t)(i0 + 2 * j + 1) * HW];
                q[j] = pack2(f0, f1);
            }
            *(uint4*)(smem + OFF_X + off_rk(w, i0)) = *(uint4*)q;
        }
    }
    __syncthreads();  // weights ready for toep build

    build_toep(smem, whh, whl, t);
    __syncthreads();

    // ---- Stage 1: Y[h][w] = Toep(wh*2^8) @ X^T^T.  Warp tile 32(m) x 64(n). ----
    int liA = lane & 15, khA = lane >> 4;
    int nB = lane & 7, khB = (lane & 15) >> 3, tB = lane >> 4;

    int mwb = (wid & 3) * 32, nwb = (wid >> 2) * 64;
    float d1[2][8][4];
#pragma unroll
    for (int tm = 0; tm < 2; tm++)
#pragma unroll
        for (int tn = 0; tn < 8; tn++)
#pragma unroll
            for (int q = 0; q < 4; q++) d1[tm][tn][q] = bhc;

    {
        uint32_t aRow = (uint32_t)(mwb + liA) * 256;
        uint32_t bRow = (uint32_t)(nwb + 8 * tB + nB) * 256;
#pragma unroll
        for (int kk = 0; kk < 8; kk++) {
            uint32_t ax = (uint32_t)(((2 * kk + khA) ^ (liA & 7)) << 4);
            uint32_t bx = (uint32_t)(((2 * kk + khB) ^ nB) << 4);
            uint32_t ah[2][4], al[2][4], bb[4][4];
#pragma unroll
            for (int tm = 0; tm < 2; tm++) {
                ldsm4(ah[tm], sb + OFF_TH + aRow + tm * 4096 + ax);
                ldsm4(al[tm], sb + OFF_TL + aRow + tm * 4096 + ax);
            }
#pragma unroll
            for (int g = 0; g < 4; g++) ldsm4(bb[g], sb + OFF_X + bRow + g * 4096 + bx);
#pragma unroll
            for (int tm = 0; tm < 2; tm++)
#pragma unroll
                for (int g = 0; g < 4; g++)
#pragma unroll
                    for (int s = 0; s < 2; s++) {
                        mma_f16(d1[tm][2 * g + s], ah[tm], bb[g][2 * s], bb[g][2 * s + 1]);
                        mma_f16(d1[tm][2 * g + s], al[tm], bb[g][2 * s], bb[g][2 * s + 1]);
                    }
        }
    }
    __syncthreads();  // planes free

    // Mid-epilogue: Y = d1 * 2^-8 -> fp16 single plane (OFF_X), k-major [h][w]
    {
        int ro = lane >> 2, co = (lane & 3) * 2;
#pragma unroll
        for (int tm = 0; tm < 2; tm++)
#pragma unroll
            for (int tn = 0; tn < 8; tn++) {
                int r0 = mwb + tm * 16 + ro;
                int c0 = nwb + tn * 8 + co;
                *(uint32_t*)(smem + OFF_X + off_rk(r0, c0)) =
                    pack2(d1[tm][tn][0] * WINV, d1[tm][tn][1] * WINV);
                *(uint32_t*)(smem + OFF_X + off_rk(r0 + 8, c0)) =
                    pack2(d1[tm][tn][2] * WINV, d1[tm][tn][3] * WINV);
            }
    }
    build_toep(smem, wwh, wwl, t);
    __syncthreads();

    // ---- Stage 2: Z[h][w'] = Y @ Toep(ww*2^8)^T.  Warp tile 64(m) x 32(n). ----
    int mwb2 = (wid & 1) * 64, nwb2 = (wid >> 1) * 32;
    float d2[4][4][4];
#pragma unroll
    for (int tm = 0; tm < 4; tm++)
#pragma unroll
        for (int tn = 0; tn < 4; tn++)
#pragma unroll
            for (int q = 0; q < 4; q++) d2[tm][tn][q] = bwc;

    {
        uint32_t aRow = (uint32_t)(mwb2 + liA) * 256;
        uint32_t bRow = (uint32_t)(nwb2 + 8 * tB + nB) * 256;
#pragma unroll
        for (int kk = 0; kk < 8; kk++) {
            uint32_t ax = (uint32_t)(((2 * kk + khA) ^ (liA & 7)) << 4);
            uint32_t bx = (uint32_t)(((2 * kk + khB) ^ nB) << 4);
            uint32_t af[4][4], bh_[2][4], bl_[2][4];
#pragma unroll
            for (int tm = 0; tm < 4; tm++)
                ldsm4(af[tm], sb + OFF_X + aRow + tm * 4096 + ax);
#pragma unroll
            for (int tp = 0; tp < 2; tp++) {
                ldsm4(bh_[tp], sb + OFF_TH + bRow + tp * 4096 + bx);
                ldsm4(bl_[tp], sb + OFF_TL + bRow + tp * 4096 + bx);
            }
#pragma unroll
            for (int tm = 0; tm < 4; tm++)
#pragma unroll
                for (int tn = 0; tn < 4; tn++) {
                    uint32_t b0h = bh_[tn >> 1][(tn & 1) * 2], b1h = bh_[tn >> 1][(tn & 1) * 2 + 1];
                    uint32_t b0l = bl_[tn >> 1][(tn & 1) * 2], b1l = bl_[tn >> 1][(tn & 1) * 2 + 1];
                    mma_f16(d2[tm][tn], af[tm], b0h, b1h);
                    mma_f16(d2[tm][tn], af[tm], b0l, b1l);
                }
        }
    }

    // Final epilogue: Z = d2 * 2^-8 -> global (float2 stores)
    {
        int ro = lane >> 2, co = (lane & 3) * 2;
#pragma unroll
        for (int tm = 0; tm < 4; tm++)
#pragma unroll
            for (int tn = 0; tn < 4; tn++) {
                int r0 = mwb2 + tm * 16 + ro;
                int c0 = nwb2 + tn * 8 + co;
                float2 v0 = make_float2(d2[tm][tn][0] * WINV, d2[tm][tn][1] * WINV);
                float2 v1 = make_float2(d2[tm][tn][2] * WINV, d2[tm][tn][3] * WINV);
                *(float2*)(out + base + (size_t)r0 * HW + c0) = v0;
                *(float2*)(out + base + (size_t)(r0 + 8) * HW + c0) = v1;
            }
    }
}

extern "C" void kernel_launch(void* const* d_in, const int* in_sizes, int n_in,
                              void* d_out, int out_size) {
    const float* x  = (const float*)d_in[0];
    const float* wh = (const float*)d_in[1];
    const float* bh = (const float*)d_in[2];
    const float* ww = (const float*)d_in[3];
    const float* bw = (const float*)d_in[4];
    float* out = (float*)d_out;

    int nimg = in_sizes[0] >> 14;
    cudaFuncSetAttribute(conv_mma_kernel,
                         cudaFuncAttributeMaxDynamicSharedMemorySize, SMEM_TOTAL);
    conv_mma_kernel<<<nimg, NTHR, SMEM_TOTAL>>>(x, wh, bh, ww, bw, out);
}

// round 7
// speedup vs baseline: 4.5261x; 1.5748x over previous
#include <cuda_runtime.h>
#include <cuda_fp16.h>
#include <cstdint>

#define HW 128
#define KSZ 255
#define NTHR 256

// smem byte offsets
#define OFF_WH 0
#define OFF_WW 512
#define OFF_T  4096              // Toeplitz plane (32KB)
#define OFF_X  (4096 + 32768)    // X^T / Y plane (32KB)
#define SMEM_TOTAL (4096 + 65536)  // 69632 -> 2 CTAs/SM

// K-major fp16 plane: 128 rows x 256B; 16B chunks XOR-swizzled by row&7.
__device__ __forceinline__ uint32_t off_rk(int r, int k) {
    return (uint32_t)(r * 256 + ((((k >> 3) ^ (r & 7)) << 4) | ((k & 7) << 1)));
}

__device__ __forceinline__ uint32_t s2u(const void* p) {
    uint32_t a;
    asm("{ .reg .u64 t; cvta.to.shared.u64 t, %1; cvt.u32.u64 %0, t; }" : "=r"(a) : "l"(p));
    return a;
}

__device__ __forceinline__ void ldsm4(uint32_t* r, uint32_t a) {
    asm volatile("ldmatrix.sync.aligned.m8n8.x4.shared.b16 {%0,%1,%2,%3},[%4];"
                 : "=r"(r[0]), "=r"(r[1]), "=r"(r[2]), "=r"(r[3]) : "r"(a));
}

__device__ __forceinline__ void mma_f16(float* d, const uint32_t* a, uint32_t b0, uint32_t b1) {
    asm volatile(
        "mma.sync.aligned.m16n8k16.row.col.f32.f16.f16.f32 "
        "{%0,%1,%2,%3},{%4,%5,%6,%7},{%8,%9},{%0,%1,%2,%3};"
        : "+f"(d[0]), "+f"(d[1]), "+f"(d[2]), "+f"(d[3])
        : "r"(a[0]), "r"(a[1]), "r"(a[2]), "r"(a[3]), "r"(b0), "r"(b1));
}

__device__ __forceinline__ uint32_t pack2(float a, float b) {
    __half2 h = __floats2half2_rn(a, b);
    return *(uint32_t*)&h;
}
__device__ __forceinline__ uint32_t pckh(__half a, __half b) {
    __half2 h = __halves2half2(a, b);
    return *(uint32_t*)&h;
}

// Build Toeplitz operand T[r][k] = ws[127 + k - r] (single fp16 plane).
__device__ __forceinline__ void build_toep(char* smem, const __half* sh, int t) {
#pragma unroll 4
    for (int it = 0; it < 32; it++) {
        int id = t + NTHR * it;            // 0..8191
        int r = id >> 6, k0 = (id & 63) << 1;
        int i0 = 127 + k0 - r;
        *(uint32_t*)(smem + OFF_T + off_rk(r, k0)) = pckh(sh[i0], sh[i0 + 1]);
    }
}

extern "C" __global__ void __launch_bounds__(NTHR, 2)
conv_mma_kernel(const float* __restrict__ x,
                const float* __restrict__ wh, const float* __restrict__ bh,
                const float* __restrict__ ww, const float* __restrict__ bw,
                float* __restrict__ out) {
    extern __shared__ __align__(1024) char smem[];
    uint32_t sb = s2u(smem);
    int t = threadIdx.x, lane = t & 31, wid = t >> 5;
    int img = blockIdx.x, c = img & 255;
    size_t base = (size_t)img << 14;

    __half* whh = (__half*)(smem + OFF_WH);
    __half* wwh = (__half*)(smem + OFF_WW);
    if (t < KSZ) {
        whh[t] = __float2half_rn(wh[c * KSZ + t]);
        wwh[t] = __float2half_rn(ww[c * KSZ + t]);
    }
    float bhc = bh[c], bwc = bw[c];

    // X^T fp16 plane: B[w][i] = f16(X[i][w]); one STS.128 per 8-i chunk.
    {
        int w = t & 127, ihalf = t >> 7;
        const float* xp = x + base + w;
#pragma unroll
        for (int blk = 0; blk < 8; blk++) {
            int i0 = ihalf * 64 + blk * 8;
            uint32_t q[4];
#pragma unroll
            for (int j = 0; j < 4; j++) {
                float f0 = xp[(size_t)(i0 + 2 * j) * HW];
                float f1 = xp[(size_t)(i0 + 2 * j + 1) * HW];
                q[j] = pack2(f0, f1);
            }
            *(uint4*)(smem + OFF_X + off_rk(w, i0)) = *(uint4*)q;
        }
    }
    __syncthreads();  // weights visible

    build_toep(smem, whh, t);
    __syncthreads();

    int liA = lane & 15, khA = lane >> 4;
    int nB = lane & 7, khB = (lane & 15) >> 3, tB = lane >> 4;

    // ---- Stage 1: Y[h][w] = Toep(wh) @ X.  Warp tile 32(m) x 64(n). ----
    int mwb = (wid & 3) * 32, nwb = (wid >> 2) * 64;
    float d1[2][8][4];
#pragma unroll
    for (int tm = 0; tm < 2; tm++)
#pragma unroll
        for (int tn = 0; tn < 8; tn++)
#pragma unroll
            for (int q = 0; q < 4; q++) d1[tm][tn][q] = bhc;

    {
        uint32_t aRow = (uint32_t)(mwb + liA) * 256;
        uint32_t bRow = (uint32_t)(nwb + 8 * tB + nB) * 256;
        uint32_t acur[4], aprev[4];
        {   // kk=0: F(0) for tm=0, F(-1) (= rows mwb+16 at k-block 0) for tm=1
            uint32_t ax0 = (uint32_t)((khA ^ (liA & 7)) << 4);
            ldsm4(acur, sb + OFF_T + aRow + ax0);
            ldsm4(aprev, sb + OFF_T + aRow + 4096 + ax0);
        }
#pragma unroll
        for (int kk = 0; kk < 8; kk++) {
            if (kk) {
#pragma unroll
                for (int i = 0; i < 4; i++) aprev[i] = acur[i];
                uint32_t ax = (uint32_t)(((2 * kk + khA) ^ (liA & 7)) << 4);
                ldsm4(acur, sb + OFF_T + aRow + ax);
            }
            uint32_t bx = (uint32_t)(((2 * kk + khB) ^ nB) << 4);
            uint32_t bb[4][4];
#pragma unroll
            for (int g = 0; g < 4; g++) ldsm4(bb[g], sb + OFF_X + bRow + g * 4096 + bx);
#pragma unroll
            for (int g = 0; g < 4; g++)
#pragma unroll
                for (int s = 0; s < 2; s++) {
                    mma_f16(d1[0][2 * g + s], acur, bb[g][2 * s], bb[g][2 * s + 1]);
                    mma_f16(d1[1][2 * g + s], aprev, bb[g][2 * s], bb[g][2 * s + 1]);
                }
        }
    }
    __syncthreads();  // planes free

    // Mid-epilogue: Y -> fp16 plane (OFF_X), k-major [h][w]
    {
        int ro = lane >> 2, co = (lane & 3) * 2;
#pragma unroll
        for (int tm = 0; tm < 2; tm++)
#pragma unroll
            for (int tn = 0; tn < 8; tn++) {
                int r0 = mwb + tm * 16 + ro;
                int c0 = nwb + tn * 8 + co;
                *(uint32_t*)(smem + OFF_X + off_rk(r0, c0)) =
                    pack2(d1[tm][tn][0], d1[tm][tn][1]);
                *(uint32_t*)(smem + OFF_X + off_rk(r0 + 8, c0)) =
                    pack2(d1[tm][tn][2], d1[tm][tn][3]);
            }
    }
    build_toep(smem, wwh, t);
    __syncthreads();

    // ---- Stage 2: Z[h][w'] = Y @ Toep(ww)^T.  Warp tile 64(m) x 32(n). ----
    int mwb2 = (wid & 1) * 64, nwb2 = (wid >> 1) * 32;
    float d2[4][4][4];
#pragma unroll
    for (int tm = 0; tm < 4; tm++)
#pragma unroll
        for (int tn = 0; tn < 4; tn++)
#pragma unroll
            for (int q = 0; q < 4; q++) d2[tm][tn][q] = bwc;

    {
        uint32_t aRow = (uint32_t)(mwb2 + liA) * 256;
        uint32_t bRow = (uint32_t)(nwb2 + 8 * tB + nB) * 256;
        uint32_t bcur[4], bprev[4];
        {   // kk=0: G(0) for tp=0, G(-1) (= rows nwb2+16 at k-block 0) for tp=1
            uint32_t bx0 = (uint32_t)((khB ^ nB) << 4);
            ldsm4(bcur, sb + OFF_T + bRow + bx0);
            ldsm4(bprev, sb + OFF_T + bRow + 4096 + bx0);
        }
#pragma unroll
        for (int kk = 0; kk < 8; kk++) {
            if (kk) {
#pragma unroll
                for (int i = 0; i < 4; i++) bprev[i] = bcur[i];
                uint32_t bx = (uint32_t)(((2 * kk + khB) ^ nB) << 4);
                ldsm4(bcur, sb + OFF_T + bRow + bx);
            }
            uint32_t ax = (uint32_t)(((2 * kk + khA) ^ (liA & 7)) << 4);
            uint32_t af[4][4];
#pragma unroll
            for (int tm = 0; tm < 4; tm++)
                ldsm4(af[tm], sb + OFF_X + aRow + tm * 4096 + ax);
#pragma unroll
            for (int tm = 0; tm < 4; tm++)
#pragma unroll
                for (int tn = 0; tn < 4; tn++) {
                    const uint32_t* bf = (tn < 2) ? bcur : bprev;
                    mma_f16(d2[tm][tn], af[tm], bf[(tn & 1) * 2], bf[(tn & 1) * 2 + 1]);
                }
        }
    }

    // Final epilogue: Z -> global (float2 stores)
    {
        int ro = lane >> 2, co = (lane & 3) * 2;
#pragma unroll
        for (int tm = 0; tm < 4; tm++)
#pragma unroll
            for (int tn = 0; tn < 4; tn++) {
                int r0 = mwb2 + tm * 16 + ro;
                int c0 = nwb2 + tn * 8 + co;
                float2 v0 = make_float2(d2[tm][tn][0], d2[tm][tn][1]);
                float2 v1 = make_float2(d2[tm][tn][2], d2[tm][tn][3]);
                *(float2*)(out + base + (size_t)r0 * HW + c0) = v0;
                *(float2*)(out + base + (size_t)(r0 + 8) * HW + c0) = v1;
            }
    }
}

extern "C" void kernel_launch(void* const* d_in, const int* in_sizes, int n_in,
                              void* d_out, int out_size) {
    const float* x  = (const float*)d_in[0];
    const float* wh = (const float*)d_in[1];
    const float* bh = (const float*)d_in[2];
    const float* ww = (const float*)d_in[3];
    const float* bw = (const float*)d_in[4];
    float* out = (float*)d_out;

    int nimg = in_sizes[0] >> 14;
    cudaFuncSetAttribute(conv_mma_kernel,
                         cudaFuncAttributeMaxDynamicSharedMemorySize, SMEM_TOTAL);
    conv_mma_kernel<<<nimg, NTHR, SMEM_TOTAL>>>(x, wh, bh, ww, bw, out);
}

// round 8
// speedup vs baseline: 5.5521x; 1.2267x over previous
#include <cuda_runtime.h>
#include <cuda_fp16.h>
#include <cstdint>

#define HW 128
#define KSZ 255
#define NTHR 256

// smem byte offsets
#define OFF_WHP 0        // 254 fp16-pairs of wh (1016B)
#define OFF_WWP 1024     // 254 fp16-pairs of ww
#define OFF_X   4096     // X^T / Y fp16 plane (32KB)
#define SMEM_TOTAL (4096 + 32768)

// K-major fp16 plane: 128 rows x 256B; 16B chunks XOR-swizzled by row&7.
__device__ __forceinline__ uint32_t off_rk(int r, int k) {
    return (uint32_t)(r * 256 + ((((k >> 3) ^ (r & 7)) << 4) | ((k & 7) << 1)));
}

__device__ __forceinline__ uint32_t s2u(const void* p) {
    uint32_t a;
    asm("{ .reg .u64 t; cvta.to.shared.u64 t, %1; cvt.u32.u64 %0, t; }" : "=r"(a) : "l"(p));
    return a;
}

__device__ __forceinline__ void ldsm4(uint32_t* r, uint32_t a) {
    asm volatile("ldmatrix.sync.aligned.m8n8.x4.shared.b16 {%0,%1,%2,%3},[%4];"
                 : "=r"(r[0]), "=r"(r[1]), "=r"(r[2]), "=r"(r[3]) : "r"(a));
}

__device__ __forceinline__ void mma_f16(float* d, uint32_t a0, uint32_t a1, uint32_t a2,
                                        uint32_t a3, uint32_t b0, uint32_t b1) {
    asm volatile(
        "mma.sync.aligned.m16n8k16.row.col.f32.f16.f16.f32 "
        "{%0,%1,%2,%3},{%4,%5,%6,%7},{%8,%9},{%0,%1,%2,%3};"
        : "+f"(d[0]), "+f"(d[1]), "+f"(d[2]), "+f"(d[3])
        : "r"(a0), "r"(a1), "r"(a2), "r"(a3), "r"(b0), "r"(b1));
}

__device__ __forceinline__ uint32_t pack2(float a, float b) {
    __half2 h = __floats2half2_rn(a, b);
    return *(uint32_t*)&h;
}

__device__ __forceinline__ uint32_t lds32(uint32_t addr) {
    uint32_t v;
    asm volatile("ld.shared.b32 %0, [%1];" : "=r"(v) : "r"(addr));
    return v;
}

extern "C" __global__ void __launch_bounds__(NTHR, 2)
conv_mma_kernel(const float* __restrict__ x,
                const float* __restrict__ wh, const float* __restrict__ bh,
                const float* __restrict__ ww, const float* __restrict__ bw,
                float* __restrict__ out) {
    extern __shared__ __align__(1024) char smem[];
    uint32_t sb = s2u(smem);
    int t = threadIdx.x, lane = t & 31, wid = t >> 5;
    int img = blockIdx.x, c = img & 255;
    size_t base = (size_t)img << 14;

    // Weight pair tables: whp[i] = (f16(wh[i]), f16(wh[i+1])), i in [0,253].
    if (t < KSZ - 1) {
        const float* wp = wh + c * KSZ;
        *(uint32_t*)(smem + OFF_WHP + 4 * t) = pack2(wp[t], wp[t + 1]);
        wp = ww + c * KSZ;
        *(uint32_t*)(smem + OFF_WWP + 4 * t) = pack2(wp[t], wp[t + 1]);
    }
    float bhc = bh[c], bwc = bw[c];

    // X^T fp16 plane: plane[w][i] = f16(X[i][w]); one STS.128 per 8-i chunk.
    {
        int w = t & 127, ihalf = t >> 7;
        const float* xp = x + base + w;
#pragma unroll
        for (int blk = 0; blk < 8; blk++) {
            int i0 = ihalf * 64 + blk * 8;
            uint32_t q[4];
#pragma unroll
            for (int j = 0; j < 4; j++) {
                float f0 = xp[(size_t)(i0 + 2 * j) * HW];
                float f1 = xp[(size_t)(i0 + 2 * j + 1) * HW];
                q[j] = pack2(f0, f1);
            }
            *(uint4*)(smem + OFF_X + off_rk(w, i0)) = *(uint4*)q;
        }
    }
    __syncthreads();

    int liA = lane & 15, khA = lane >> 4;
    int nB = lane & 7, khB = (lane & 15) >> 3, tB = lane >> 4;

    // ---- Stage 1: Y[h][w] = Toep(wh) @ X.  Warp grid 2(m) x 4(n): tile 64m x 32n. ----
    int mwb = (wid >> 2) * 64, nwb = (wid & 3) * 32;
    float d1[4][4][4];
#pragma unroll
    for (int tm = 0; tm < 4; tm++)
#pragma unroll
        for (int tn = 0; tn < 4; tn++)
#pragma unroll
            for (int q = 0; q < 4; q++) d1[tm][tn][q] = bhc;

    {
        // A-frag ring over pair table: idx(j) = ibase + 8j (word index), W[m] <-> j = 2kk+1-m
        uint32_t pw = sb + OFF_WHP;
        int ibase = 127 + 2 * (lane & 3) - (mwb + (lane >> 2));
        uint32_t W[9];
#pragma unroll
        for (int m = 2; m < 9; m++) W[m] = lds32(pw + 4u * (uint32_t)(ibase + 8 * (1 - m)));

        uint32_t bRow = (uint32_t)(nwb + 8 * tB + nB) * 256;
#pragma unroll
        for (int kk = 0; kk < 8; kk++) {
            if (kk) {
#pragma unroll
                for (int m = 8; m >= 2; m--) W[m] = W[m - 2];
            }
            W[1] = lds32(pw + 4u * (uint32_t)(ibase + 8 * (2 * kk)));
            W[0] = lds32(pw + 4u * (uint32_t)(ibase + 8 * (2 * kk + 1)));

            uint32_t bx = (uint32_t)(((2 * kk + khB) ^ nB) << 4);
            uint32_t bb[2][4];
#pragma unroll
            for (int g = 0; g < 2; g++) ldsm4(bb[g], sb + OFF_X + bRow + g * 4096 + bx);
#pragma unroll
            for (int tm = 0; tm < 4; tm++) {
                uint32_t a0 = W[1 + 2 * tm], a1 = W[2 + 2 * tm], a2 = W[2 * tm];
#pragma unroll
                for (int tn = 0; tn < 4; tn++)
                    mma_f16(d1[tm][tn], a0, a1, a2, a0,
                            bb[tn >> 1][(tn & 1) * 2], bb[tn >> 1][(tn & 1) * 2 + 1]);
            }
        }
    }
    __syncthreads();  // X plane reads done

    // Mid-epilogue: Y -> fp16 plane (OFF_X), k-major [h][w]
    {
        int ro = lane >> 2, co = (lane & 3) * 2;
#pragma unroll
        for (int tm = 0; tm < 4; tm++)
#pragma unroll
            for (int tn = 0; tn < 4; tn++) {
                int r0 = mwb + tm * 16 + ro;
                int c0 = nwb + tn * 8 + co;
                *(uint32_t*)(smem + OFF_X + off_rk(r0, c0)) =
                    pack2(d1[tm][tn][0], d1[tm][tn][1]);
                *(uint32_t*)(smem + OFF_X + off_rk(r0 + 8, c0)) =
                    pack2(d1[tm][tn][2], d1[tm][tn][3]);
            }
    }
    __syncthreads();

    // ---- Stage 2: Z[h][w'] = Y @ Toep(ww)^T.  Warp grid 4(m) x 2(n): tile 32m x 64n. ----
    int mwb2 = (wid & 3) * 32, nwb2 = (wid >> 2) * 64;
    float d2[2][8][4];
#pragma unroll
    for (int tm = 0; tm < 2; tm++)
#pragma unroll
        for (int tn = 0; tn < 8; tn++)
#pragma unroll
            for (int q = 0; q < 4; q++) d2[tm][tn][q] = bwc;

    {
        uint32_t pw = sb + OFF_WWP;
        int ibase = 127 + 2 * (lane & 3) - (nwb2 + (lane >> 2));
        uint32_t W[9];
#pragma unroll
        for (int m = 2; m < 9; m++) W[m] = lds32(pw + 4u * (uint32_t)(ibase + 8 * (1 - m)));

        uint32_t aRow = (uint32_t)(mwb2 + liA) * 256;
#pragma unroll
        for (int kk = 0; kk < 8; kk++) {
            if (kk) {
#pragma unroll
                for (int m = 8; m >= 2; m--) W[m] = W[m - 2];
            }
            W[1] = lds32(pw + 4u * (uint32_t)(ibase + 8 * (2 * kk)));
            W[0] = lds32(pw + 4u * (uint32_t)(ibase + 8 * (2 * kk + 1)));

            uint32_t ax = (uint32_t)(((2 * kk + khA) ^ (liA & 7)) << 4);
            uint32_t af[2][4];
#pragma unroll
            for (int tm = 0; tm < 2; tm++)
                ldsm4(af[tm], sb + OFF_X + aRow + tm * 4096 + ax);
#pragma unroll
            for (int tm = 0; tm < 2; tm++)
#pragma unroll
                for (int tn = 0; tn < 8; tn++)
                    mma_f16(d2[tm][tn], af[tm][0], af[tm][1], af[tm][2], af[tm][3],
                            W[1 + tn], W[tn]);
        }
    }

    // Final epilogue: Z -> global (float2 stores)
    {
        int ro = lane >> 2, co = (lane & 3) * 2;
#pragma unroll
        for (int tm = 0; tm < 2; tm++)
#pragma unroll
            for (int tn = 0; tn < 8; tn++) {
                int r0 = mwb2 + tm * 16 + ro;
                int c0 = nwb2 + tn * 8 + co;
                float2 v0 = make_float2(d2[tm][tn][0], d2[tm][tn][1]);
                float2 v1 = make_float2(d2[tm][tn][2], d2[tm][tn][3]);
                *(float2*)(out + base + (size_t)r0 * HW + c0) = v0;
                *(float2*)(out + base + (size_t)(r0 + 8) * HW + c0) = v1;
            }
    }
}

extern "C" void kernel_launch(void* const* d_in, const int* in_sizes, int n_in,
                              void* d_out, int out_size) {
    const float* x  = (const float*)d_in[0];
    const float* wh = (const float*)d_in[1];
    const float* bh = (const float*)d_in[2];
    const float* ww = (const float*)d_in[3];
    const float* bw = (const float*)d_in[4];
    float* out = (float*)d_out;

    int nimg = in_sizes[0] >> 14;
    cudaFuncSetAttribute(conv_mma_kernel,
                         cudaFuncAttributeMaxDynamicSharedMemorySize, SMEM_TOTAL);
    conv_mma_kernel<<<nimg, NTHR, SMEM_TOTAL>>>(x, wh, bh, ww, bw, out);
}